// round 3
// baseline (speedup 1.0000x reference)
#include <cuda_runtime.h>

#define PS 5
#define NT 2
#define PH 536
#define PW 536
#define OH 532
#define OW 532
#define PDIM 75
#define HW (PH*PW)

#define TX 32
#define TY 8
#define TXH (TX+4)           // 36
#define TYH (TY+4)           // 12
#define NROWS (TXH*TYH)      // 432
#define RSTRIDE 77           // 76 payload + 1 pad -> conflict-free gather
#define THREADS 256
#define SMEM_BYTES (NROWS*RSTRIDE*4)   // 133056 B

#define MEANS_CHUNKS 8       // partial-sum blocks per (t,c)

__device__ float g_part[6 * MEANS_CHUNKS];
__device__ float g_means[6];

// ---------------- means: partial sums (deterministic, no atomics) ------------
__global__ void means_partial_kernel(const float* __restrict__ noisy) {
    int tc    = blockIdx.x;          // 0..5
    int chunk = blockIdx.y;          // 0..MEANS_CHUNKS-1
    const int plane = OH * OW;       // 283024, divisible by 4
    const float4* p = (const float4*)(noisy + (size_t)tc * plane);
    const int n4 = plane / 4;        // 70756
    float s = 0.f;
    for (int i = chunk * blockDim.x + threadIdx.x; i < n4;
         i += gridDim.y * blockDim.x) {
        float4 v = p[i];
        s += (v.x + v.y) + (v.z + v.w);
    }
    // block reduce
    __shared__ float red[32];
    #pragma unroll
    for (int o = 16; o; o >>= 1) s += __shfl_down_sync(0xffffffffu, s, o);
    if ((threadIdx.x & 31) == 0) red[threadIdx.x >> 5] = s;
    __syncthreads();
    if (threadIdx.x < 32) {
        float v = (threadIdx.x < (int)(blockDim.x >> 5)) ? red[threadIdx.x] : 0.f;
        #pragma unroll
        for (int o = 16; o; o >>= 1) v += __shfl_down_sync(0xffffffffu, v, o);
        if (threadIdx.x == 0) g_part[tc * MEANS_CHUNKS + chunk] = v;
    }
}

__global__ void means_reduce_kernel() {
    int tc = threadIdx.x;
    if (tc < 6) {
        float s = 0.f;
        #pragma unroll
        for (int k = 0; k < MEANS_CHUNKS; k++) s += g_part[tc * MEANS_CHUNKS + k];
        g_means[tc] = s * (1.0f / (float)(OH * OW));
    }
}

// ---------------- main fold/gather kernel -----------------------------------
extern __shared__ float smem[];

__global__ void __launch_bounds__(THREADS, 1)
fold_kernel(const float* __restrict__ deno,
            const float* __restrict__ pwts,
            float* __restrict__ out) {
    const int t  = blockIdx.z;
    const int x0 = blockIdx.x * TX;      // output X' base
    const int y0 = blockIdx.y * TY;      // output Y' base

    const float* dptr = deno + (size_t)t * HW * PDIM;
    const float* wptr = pwts + (size_t)t * HW;

    // Clamp staging window so it stays in-bounds (edge tiles shift; interior xoff/yoff = 0)
    const int ybase = min(y0, PH - TYH);
    const int xbase = min(x0, PW - TXH);
    const int yoff  = y0 - ybase;
    const int xoff  = x0 - xbase;

    // ---- stage (TYH x TXH) patch rows: 75 deno floats + weight per row ----
    for (int ly = 0; ly < TYH; ly++) {
        const int rbase = (ybase + ly) * PW + xbase;
        const float* src = dptr + (size_t)rbase * PDIM;   // TXH*PDIM contiguous floats
        float* drow = smem + ly * TXH * RSTRIDE;
        for (int idx = threadIdx.x; idx < TXH * PDIM; idx += THREADS) {
            int lx   = idx / PDIM;
            int slot = idx - lx * PDIM;
            drow[lx * RSTRIDE + slot] = src[idx];
        }
        for (int lx = threadIdx.x; lx < TXH; lx += THREADS) {
            drow[lx * RSTRIDE + PDIM] = wptr[rbase + lx];
        }
    }
    __syncthreads();

    // ---- gather: one output pixel per thread, 3 channels + cnt ----
    const int tx = threadIdx.x & (TX - 1);
    const int ty = threadIdx.x / TX;
    const int Xo = x0 + tx;
    const int Yo = y0 + ty;

    // GUARD the whole gather: out-of-range threads would index smem
    // beyond the (clamped) staged window.
    if (Xo < OW && Yo < OH) {
        const int lyb = yoff + ty;   // relative row of Yo in window
        const int lxb = xoff + tx;   // relative col of Xo in window

        float a0 = 0.f, a1 = 0.f, a2 = 0.f, cnt = 0.f;
        #pragma unroll
        for (int i = 0; i < PS; i++) {
            #pragma unroll
            for (int j = 0; j < PS; j++) {
                const float* row =
                    &smem[((lyb + 4 - i) * TXH + (lxb + 4 - j)) * RSTRIDE];
                const float w = row[PDIM];
                const int s = i * PS + j;
                cnt += w;
                a0 = fmaf(row[s],      w, a0);
                a1 = fmaf(row[25 + s], w, a1);
                a2 = fmaf(row[50 + s], w, a2);
            }
        }

        const float inv = 0.5f / cnt;
        const size_t plane = (size_t)OH * OW;
        size_t o = (size_t)t * 3 * plane + (size_t)Yo * OW + Xo;
        const int tb = t * 3;
        out[o]             = a0 * inv + g_means[tb + 0];
        out[o + plane]     = a1 * inv + g_means[tb + 1];
        out[o + 2 * plane] = a2 * inv + g_means[tb + 2];
    }
}

// ---------------- launch ------------------------------------------------------
extern "C" void kernel_launch(void* const* d_in, const int* in_sizes, int n_in,
                              void* d_out, int out_size) {
    const float* noisy = (const float*)d_in[0];
    const float* deno  = (const float*)d_in[1];
    const float* pwts  = (const float*)d_in[2];
    float* out = (float*)d_out;

    cudaFuncSetAttribute(fold_kernel,
                         cudaFuncAttributeMaxDynamicSharedMemorySize,
                         SMEM_BYTES);

    dim3 mg(6, MEANS_CHUNKS);
    means_partial_kernel<<<mg, 256>>>(noisy);
    means_reduce_kernel<<<1, 32>>>();

    dim3 grid((OW + TX - 1) / TX, (OH + TY - 1) / TY, NT);
    fold_kernel<<<grid, THREADS, SMEM_BYTES>>>(deno, pwts, out);
}

// round 5
// speedup vs baseline: 5.1817x; 5.1817x over previous
#include <cuda_runtime.h>
#include <cstdint>

#define PS 5
#define NT 2
#define PH 536
#define PW 536
#define OH 532
#define OW 532
#define PDIM 75
#define HW (PH*PW)

#define TX 32
#define TY 16
#define TXH (TX+4)           // 36
#define TYH (TY+4)           // 20
#define CHUNK (TXH*PDIM)     // 2700 floats per staged row-chunk
#define THREADS 512
// smem: TYH chunks of CHUNK floats (deno rows, natural stride 75) + TYH*TXH weights
#define SMEM_FLOATS (TYH*CHUNK + TYH*TXH)
#define SMEM_BYTES  (SMEM_FLOATS*4)          // 218,880 B

#define MEANS_CHUNKS 25      // 6*25 = 150 blocks -> fills the chip

__device__ float g_part[6 * MEANS_CHUNKS];
__device__ float g_means[6];

// ---------------- cp.async helpers ------------------------------------------
__device__ __forceinline__ void cpa4(float* dst_smem, const float* src_gmem) {
    uint32_t d = (uint32_t)__cvta_generic_to_shared(dst_smem);
    asm volatile("cp.async.ca.shared.global [%0], [%1], 4;\n"
                 :: "r"(d), "l"(src_gmem));
}
__device__ __forceinline__ void cpa_commit_wait() {
    asm volatile("cp.async.commit_group;\n");
    asm volatile("cp.async.wait_group 0;\n");
}

// ---------------- means: partial sums (deterministic, no atomics) ------------
__global__ void means_partial_kernel(const float* __restrict__ noisy) {
    int tc    = blockIdx.x;          // 0..5
    int chunk = blockIdx.y;          // 0..MEANS_CHUNKS-1
    const int plane = OH * OW;       // 283024, divisible by 4
    const float4* p = (const float4*)(noisy + (size_t)tc * plane);
    const int n4 = plane / 4;        // 70756
    float s = 0.f;
    for (int i = chunk * blockDim.x + threadIdx.x; i < n4;
         i += gridDim.y * blockDim.x) {
        float4 v = p[i];
        s += (v.x + v.y) + (v.z + v.w);
    }
    __shared__ float red[32];
    #pragma unroll
    for (int o = 16; o; o >>= 1) s += __shfl_down_sync(0xffffffffu, s, o);
    if ((threadIdx.x & 31) == 0) red[threadIdx.x >> 5] = s;
    __syncthreads();
    if (threadIdx.x < 32) {
        float v = (threadIdx.x < (int)(blockDim.x >> 5)) ? red[threadIdx.x] : 0.f;
        #pragma unroll
        for (int o = 16; o; o >>= 1) v += __shfl_down_sync(0xffffffffu, v, o);
        if (threadIdx.x == 0) g_part[tc * MEANS_CHUNKS + chunk] = v;
    }
}

__global__ void means_reduce_kernel() {
    int tc = threadIdx.x;
    if (tc < 6) {
        float s = 0.f;
        #pragma unroll
        for (int k = 0; k < MEANS_CHUNKS; k++) s += g_part[tc * MEANS_CHUNKS + k];
        g_means[tc] = s * (1.0f / (float)(OH * OW));
    }
}

// ---------------- main fold/gather kernel -----------------------------------
extern __shared__ float smem[];

__global__ void __launch_bounds__(THREADS, 1)
fold_kernel(const float* __restrict__ deno,
            const float* __restrict__ pwts,
            float* __restrict__ out) {
    const int t  = blockIdx.z;
    const int x0 = blockIdx.x * TX;
    const int y0 = blockIdx.y * TY;

    const float* dptr = deno + (size_t)t * HW * PDIM;
    const float* wptr = pwts + (size_t)t * HW;

    // Clamp staging window in-bounds; edge tiles shift (interior offs = 0)
    const int ybase = min(y0, PH - TYH);
    const int xbase = min(x0, PW - TXH);
    const int yoff  = y0 - ybase;
    const int xoff  = x0 - xbase;

    float* sval = smem;                     // TYH chunks of CHUNK floats
    float* swt  = smem + TYH * CHUNK;       // TYH*TXH weights

    const int tid = threadIdx.x;

    // ---- stage via cp.async: verbatim contiguous copies, no restride ----
    #pragma unroll
    for (int c = 0; c < TYH; c++) {
        const int rbase = (ybase + c) * PW + xbase;
        const float* src = dptr + (size_t)rbase * PDIM;   // CHUNK contiguous floats
        float* dst = sval + c * CHUNK;
        #pragma unroll
        for (int i = tid; i < CHUNK; i += THREADS) cpa4(dst + i, src + i);
        if (tid < TXH) cpa4(&swt[c * TXH + tid], &wptr[rbase + tid]);
    }
    cpa_commit_wait();
    __syncthreads();

    // ---- gather: one output pixel per thread ----
    const int tx = tid & (TX - 1);
    const int ty = tid / TX;
    const int Xo = x0 + tx;
    const int Yo = y0 + ty;

    if (Xo < OW && Yo < OH) {
        const int lyb = yoff + ty;   // window-relative row of Yo
        const int lxb = xoff + tx;   // window-relative col of Xo

        float a0 = 0.f, a1 = 0.f, a2 = 0.f, cnt = 0.f;
        #pragma unroll
        for (int i = 0; i < PS; i++) {
            const int ly = lyb + 4 - i;
            const float* vrow = sval + ly * CHUNK;
            const float* wrow = swt + ly * TXH;
            #pragma unroll
            for (int j = 0; j < PS; j++) {
                const int lx = lxb + 4 - j;
                const float w = wrow[lx];
                const float* v = vrow + lx * PDIM;   // stride 75: bank-conflict-free
                const int s = i * PS + j;
                cnt += w;
                a0 = fmaf(v[s],      w, a0);
                a1 = fmaf(v[25 + s], w, a1);
                a2 = fmaf(v[50 + s], w, a2);
            }
        }

        const float inv = 0.5f / cnt;
        const size_t plane = (size_t)OH * OW;
        size_t o = (size_t)t * 3 * plane + (size_t)Yo * OW + Xo;
        const int tb = t * 3;
        out[o]             = a0 * inv + g_means[tb + 0];
        out[o + plane]     = a1 * inv + g_means[tb + 1];
        out[o + 2 * plane] = a2 * inv + g_means[tb + 2];
    }
}

// ---------------- launch ------------------------------------------------------
extern "C" void kernel_launch(void* const* d_in, const int* in_sizes, int n_in,
                              void* d_out, int out_size) {
    const float* noisy = (const float*)d_in[0];
    const float* deno  = (const float*)d_in[1];
    const float* pwts  = (const float*)d_in[2];
    float* out = (float*)d_out;

    cudaFuncSetAttribute(fold_kernel,
                         cudaFuncAttributeMaxDynamicSharedMemorySize,
                         SMEM_BYTES);

    dim3 mg(6, MEANS_CHUNKS);
    means_partial_kernel<<<mg, 256>>>(noisy);
    means_reduce_kernel<<<1, 32>>>();

    dim3 grid((OW + TX - 1) / TX, (OH + TY - 1) / TY, NT);
    fold_kernel<<<grid, THREADS, SMEM_BYTES>>>(deno, pwts, out);
}

// round 6
// speedup vs baseline: 7.5106x; 1.4494x over previous
#include <cuda_runtime.h>
#include <cstdint>

#define PS 5
#define NT 2
#define PH 536
#define PW 536
#define OH 532
#define OW 532
#define PDIM 75
#define HW (PH*PW)

#define TX 32
#define TY 16
#define TXH (TX+4)           // 36
#define TYH (TY+4)           // 20
#define CHUNK (TXH*PDIM)     // 2700 floats per window row-chunk
#define CSTRIDE 2708         // chunk smem stride: mult of 4 (16B dst align) + slack for moff/overread
#define THREADS 512
#define GROUP_A_ROWS 12      // staging group split: rows [0,12) then [12,20)

// smem: TYH chunks (CSTRIDE floats) + TYH*TXH weights + 6 means + pad
#define SMEM_FLOATS (TYH*CSTRIDE + TYH*TXH + 8)
#define SMEM_BYTES  (SMEM_FLOATS*4)          // 219,584 B

#define MEANS_CHUNKS 32      // 6*32 = 192 blocks

__device__ float g_part[6 * MEANS_CHUNKS];

// ---------------- cp.async helpers ------------------------------------------
__device__ __forceinline__ void cpa16(void* dst_smem, const void* src_gmem) {
    uint32_t d = (uint32_t)__cvta_generic_to_shared(dst_smem);
    asm volatile("cp.async.cg.shared.global [%0], [%1], 16;\n"
                 :: "r"(d), "l"(src_gmem));
}
__device__ __forceinline__ void cpa4(void* dst_smem, const void* src_gmem) {
    uint32_t d = (uint32_t)__cvta_generic_to_shared(dst_smem);
    asm volatile("cp.async.ca.shared.global [%0], [%1], 4;\n"
                 :: "r"(d), "l"(src_gmem));
}
__device__ __forceinline__ void cpa_commit() {
    asm volatile("cp.async.commit_group;\n");
}
__device__ __forceinline__ void cpa_wait1() {
    asm volatile("cp.async.wait_group 1;\n");
}
__device__ __forceinline__ void cpa_wait0() {
    asm volatile("cp.async.wait_group 0;\n");
}

// ---------------- means: partial sums (deterministic, no atomics) ------------
__global__ void __launch_bounds__(512)
means_partial_kernel(const float* __restrict__ noisy) {
    int tc    = blockIdx.x;          // 0..5
    int chunk = blockIdx.y;          // 0..MEANS_CHUNKS-1
    const int plane = OH * OW;       // 283024, divisible by 4
    const float4* p = (const float4*)(noisy + (size_t)tc * plane);
    const int n4 = plane / 4;        // 70756
    float s = 0.f;
    #pragma unroll 4
    for (int i = chunk * 512 + threadIdx.x; i < n4;
         i += MEANS_CHUNKS * 512) {
        float4 v = p[i];
        s += (v.x + v.y) + (v.z + v.w);
    }
    __shared__ float red[32];
    #pragma unroll
    for (int o = 16; o; o >>= 1) s += __shfl_down_sync(0xffffffffu, s, o);
    if ((threadIdx.x & 31) == 0) red[threadIdx.x >> 5] = s;
    __syncthreads();
    if (threadIdx.x < 32) {
        float v = (threadIdx.x < 16) ? red[threadIdx.x] : 0.f;
        #pragma unroll
        for (int o = 16; o; o >>= 1) v += __shfl_down_sync(0xffffffffu, v, o);
        if (threadIdx.x == 0) g_part[tc * MEANS_CHUNKS + chunk] = v;
    }
}

// ---------------- main fold/gather kernel -----------------------------------
extern __shared__ float smem[];

__device__ __forceinline__ void gather_row(
    const float* sval, const float* swt, const float* smeans,
    int t, int ty, int tx, int x0, int y0, int xoff, int yoff,
    float* out)
{
    const int Xo = x0 + tx;
    const int Yo = y0 + ty;
    if (Xo >= OW || Yo >= OH) return;

    const int lyb = yoff + ty;
    const int lxb = xoff + tx;

    float a0 = 0.f, a1 = 0.f, a2 = 0.f, cnt = 0.f;
    #pragma unroll
    for (int i = 0; i < PS; i++) {
        const int ly = lyb + 4 - i;
        const float* vrow = sval + ly * CSTRIDE;
        const float* wrow = swt + ly * TXH;
        #pragma unroll
        for (int j = 0; j < PS; j++) {
            const int lx = lxb + 4 - j;
            const float w = wrow[lx];
            const float* v = vrow + lx * PDIM;   // stride 75: bank-conflict-free
            const int s = i * PS + j;
            cnt += w;
            a0 = fmaf(v[s],      w, a0);
            a1 = fmaf(v[25 + s], w, a1);
            a2 = fmaf(v[50 + s], w, a2);
        }
    }

    const float inv = 0.5f / cnt;
    const size_t plane = (size_t)OH * OW;
    size_t o = (size_t)t * 3 * plane + (size_t)Yo * OW + Xo;
    const int tb = t * 3;
    out[o]             = a0 * inv + smeans[tb + 0];
    out[o + plane]     = a1 * inv + smeans[tb + 1];
    out[o + 2 * plane] = a2 * inv + smeans[tb + 2];
}

__global__ void __launch_bounds__(THREADS, 1)
fold_kernel(const float* __restrict__ deno,
            const float* __restrict__ pwts,
            float* __restrict__ out) {
    const int t  = blockIdx.z;
    const int x0 = blockIdx.x * TX;
    const int y0 = blockIdx.y * TY;

    const float* dptr = deno + (size_t)t * HW * PDIM;
    const float* wptr = pwts + (size_t)t * HW;

    // Clamp staging window in-bounds; edge tiles shift (interior offs = 0)
    const int ybase = min(y0, PH - TYH);
    const int xbase = min(x0, PW - TXH);
    const int yoff  = y0 - ybase;
    const int xoff  = x0 - xbase;

    float* sval   = smem;                       // TYH chunks of CSTRIDE floats
    float* swt    = smem + TYH * CSTRIDE;       // TYH*TXH weights
    float* smeans = swt + TYH * TXH;            // 6 means

    const int tid = threadIdx.x;

    // moff: gmem row-base misalignment in floats — CONSTANT per block
    // (row base = rbase*75 floats; rbase ≡ xbase mod 4 since 536 ≡ 0 mod 4)
    const int moff = (xbase * 3) & 3;           // (xbase*75) mod 4
    const int nf4  = (moff + CHUNK + 3) >> 2;   // float4s per chunk (675/676)

    // ---- stage group A: window rows [0, GROUP_A_ROWS) ----
    #pragma unroll
    for (int c = 0; c < GROUP_A_ROWS; c++) {
        const int rbase = (ybase + c) * PW + xbase;
        const float4* s4 = (const float4*)(dptr + (size_t)rbase * PDIM - moff);
        float4* d4 = (float4*)(sval + c * CSTRIDE);
        for (int i = tid; i < nf4; i += THREADS) cpa16(d4 + i, s4 + i);
        if (tid < TXH) cpa4(&swt[c * TXH + tid], &wptr[rbase + tid]);
    }
    cpa_commit();

    // ---- stage group B: window rows [GROUP_A_ROWS, TYH) ----
    #pragma unroll
    for (int c = GROUP_A_ROWS; c < TYH; c++) {
        const int rbase = (ybase + c) * PW + xbase;
        const float4* s4 = (const float4*)(dptr + (size_t)rbase * PDIM - moff);
        float4* d4 = (float4*)(sval + c * CSTRIDE);
        for (int i = tid; i < nf4; i += THREADS) cpa16(d4 + i, s4 + i);
        if (tid < TXH) cpa4(&swt[c * TXH + tid], &wptr[rbase + tid]);
    }
    cpa_commit();

    // ---- while TMA... while cp.async streams: reduce means partials ----
    if (tid < 6) {
        float s = 0.f;
        #pragma unroll
        for (int k = 0; k < MEANS_CHUNKS; k++) s += g_part[tid * MEANS_CHUNKS + k];
        smeans[tid] = s * (1.0f / (float)(OH * OW));
    }

    const int tx = tid & (TX - 1);
    const int ty = tid >> 5;                    // warp id == output row
    // phase-1 eligibility: needs window rows <= yoff+ty+4 <= GROUP_A_ROWS-1
    const bool ph1 = (yoff + ty + 4 <= GROUP_A_ROWS - 1);

    const float* svalc = sval + moff;           // fold the misalignment offset in

    cpa_wait1();          // group A complete
    __syncthreads();      // visible CTA-wide (smeans too)

    if (ph1)
        gather_row(svalc, swt, smeans, t, ty, tx, x0, y0, xoff, yoff, out);

    cpa_wait0();          // group B complete
    __syncthreads();

    if (!ph1)
        gather_row(svalc, swt, smeans, t, ty, tx, x0, y0, xoff, yoff, out);
}

// ---------------- launch ------------------------------------------------------
extern "C" void kernel_launch(void* const* d_in, const int* in_sizes, int n_in,
                              void* d_out, int out_size) {
    const float* noisy = (const float*)d_in[0];
    const float* deno  = (const float*)d_in[1];
    const float* pwts  = (const float*)d_in[2];
    float* out = (float*)d_out;

    cudaFuncSetAttribute(fold_kernel,
                         cudaFuncAttributeMaxDynamicSharedMemorySize,
                         SMEM_BYTES);

    dim3 mg(6, MEANS_CHUNKS);
    means_partial_kernel<<<mg, 512>>>(noisy);

    dim3 grid((OW + TX - 1) / TX, (OH + TY - 1) / TY, NT);
    fold_kernel<<<grid, THREADS, SMEM_BYTES>>>(deno, pwts, out);
}

// round 7
// speedup vs baseline: 9.3416x; 1.2438x over previous
#include <cuda_runtime.h>
#include <cstdint>

#define PS 5
#define NT 2
#define PH 536
#define PW 536
#define OH 532
#define OW 532
#define PDIM 75
#define HW (PH*PW)

#define TX 32
#define TY 16
#define TXH (TX+4)           // 36
#define TYH (TY+4)           // 20
#define CHUNK (TXH*PDIM)     // 2700 floats per window row
#define CSTRIDE 2708         // smem row stride (16B-aligned, slack for align-down)
#define WSTRIDE 40           // weight smem row stride (160B, 16B-aligned)
#define THREADS 512
#define GROUP_A_ROWS 12      // rows [0,12) -> barrier A, [12,20) -> barrier B

// smem floats: values + weights + means(+pad) + 2 mbarriers (4 floats)
#define SVAL_OFF   0
#define SWT_OFF    (TYH*CSTRIDE)              // 54160
#define SMEANS_OFF (SWT_OFF + TYH*WSTRIDE)    // 54960
#define MBAR_OFF   (SMEANS_OFF + 8)           // 54968 (byte 219872, 16B aligned)
#define SMEM_FLOATS (MBAR_OFF + 4)
#define SMEM_BYTES  (SMEM_FLOATS*4)           // 219888 B

#define MEANS_CHUNKS 32      // 6*32 = 192 blocks

__device__ float g_part[6 * MEANS_CHUNKS];

// ---------------- PTX helpers ------------------------------------------------
__device__ __forceinline__ uint32_t smem_u32(const void* p) {
    return (uint32_t)__cvta_generic_to_shared(p);
}
__device__ __forceinline__ void mbar_init(uint32_t a, uint32_t cnt) {
    asm volatile("mbarrier.init.shared.b64 [%0], %1;" :: "r"(a), "r"(cnt) : "memory");
}
__device__ __forceinline__ void mbar_expect(uint32_t a, uint32_t bytes) {
    asm volatile("mbarrier.arrive.expect_tx.shared.b64 _, [%0], %1;"
                 :: "r"(a), "r"(bytes) : "memory");
}
__device__ __forceinline__ void mbar_wait0(uint32_t a) {
    asm volatile(
        "{\n\t.reg .pred P;\n\t"
        "WL_%=:\n\t"
        "mbarrier.try_wait.parity.shared.b64 P, [%0], 0, 0x989680;\n\t"
        "@P bra.uni WD_%=;\n\t"
        "bra.uni WL_%=;\n\t"
        "WD_%=:\n\t}"
        :: "r"(a) : "memory");
}
__device__ __forceinline__ void bulk_g2s(uint32_t dst, const void* src,
                                         uint32_t bytes, uint32_t mbar) {
    asm volatile(
        "cp.async.bulk.shared::cta.global.mbarrier::complete_tx::bytes "
        "[%0], [%1], %2, [%3];"
        :: "r"(dst), "l"(src), "r"(bytes), "r"(mbar) : "memory");
}

// ---------------- means: partial sums (deterministic, no atomics) ------------
__global__ void __launch_bounds__(512)
means_partial_kernel(const float* __restrict__ noisy) {
    int tc    = blockIdx.x;          // 0..5
    int chunk = blockIdx.y;          // 0..MEANS_CHUNKS-1
    const int plane = OH * OW;       // 283024, divisible by 4
    const float4* p = (const float4*)(noisy + (size_t)tc * plane);
    const int n4 = plane / 4;        // 70756
    float s = 0.f;
    #pragma unroll 8
    for (int i = chunk * 512 + threadIdx.x; i < n4;
         i += MEANS_CHUNKS * 512) {
        float4 v = p[i];
        s += (v.x + v.y) + (v.z + v.w);
    }
    __shared__ float red[32];
    #pragma unroll
    for (int o = 16; o; o >>= 1) s += __shfl_down_sync(0xffffffffu, s, o);
    if ((threadIdx.x & 31) == 0) red[threadIdx.x >> 5] = s;
    __syncthreads();
    if (threadIdx.x < 32) {
        float v = (threadIdx.x < 16) ? red[threadIdx.x] : 0.f;
        #pragma unroll
        for (int o = 16; o; o >>= 1) v += __shfl_down_sync(0xffffffffu, v, o);
        if (threadIdx.x == 0) g_part[tc * MEANS_CHUNKS + chunk] = v;
    }
}

// ---------------- main fold/gather kernel -----------------------------------
extern __shared__ float smem[];

__device__ __forceinline__ void gather_row(
    const float* sval, const float* swt, const float* smeans,
    int t, int ty, int tx, int x0, int y0, int xoff, int yoff,
    float* out)
{
    const int Xo = x0 + tx;
    const int Yo = y0 + ty;
    if (Xo >= OW || Yo >= OH) return;

    const int lyb = yoff + ty;
    const int lxb = xoff + tx;

    float a0 = 0.f, a1 = 0.f, a2 = 0.f, cnt = 0.f;
    #pragma unroll
    for (int i = 0; i < PS; i++) {
        const int ly = lyb + 4 - i;
        const float* vrow = sval + ly * CSTRIDE;
        const float* wrow = swt + ly * WSTRIDE;
        #pragma unroll
        for (int j = 0; j < PS; j++) {
            const int lx = lxb + 4 - j;
            const float w = wrow[lx];
            const float* v = vrow + lx * PDIM;   // stride 75: bank-conflict-free
            const int s = i * PS + j;
            cnt += w;
            a0 = fmaf(v[s],      w, a0);
            a1 = fmaf(v[25 + s], w, a1);
            a2 = fmaf(v[50 + s], w, a2);
        }
    }

    const float inv = 0.5f / cnt;
    const size_t plane = (size_t)OH * OW;
    size_t o = (size_t)t * 3 * plane + (size_t)Yo * OW + Xo;
    const int tb = t * 3;
    out[o]             = a0 * inv + smeans[tb + 0];
    out[o + plane]     = a1 * inv + smeans[tb + 1];
    out[o + 2 * plane] = a2 * inv + smeans[tb + 2];
}

__global__ void __launch_bounds__(THREADS, 1)
fold_kernel(const float* __restrict__ deno,
            const float* __restrict__ pwts,
            float* __restrict__ out) {
    const int t  = blockIdx.z;
    const int x0 = blockIdx.x * TX;
    const int y0 = blockIdx.y * TY;

    const float* dptr = deno + (size_t)t * HW * PDIM;
    const float* wptr = pwts + (size_t)t * HW;

    // Clamp staging window in-bounds; edge tiles shift (interior offs = 0)
    const int ybase = min(y0, PH - TYH);
    const int xbase = min(x0, PW - TXH);
    const int yoff  = y0 - ybase;
    const int xoff  = x0 - xbase;

    float* sval   = smem + SVAL_OFF;
    float* swt    = smem + SWT_OFF;
    float* smeans = smem + SMEANS_OFF;
    const uint32_t mbarA = smem_u32(smem + MBAR_OFF);
    const uint32_t mbarB = mbarA + 8;

    const int tid = threadIdx.x;

    // Row-base alignment (in floats). xbase is always a multiple of 4
    // (32*k or 500), so moff == woff == 0 in practice; kept general.
    const int moff = (xbase * 3) & 3;                 // (xbase*75) mod 4
    const int woff = xbase & 3;
    const uint32_t vbytes = (uint32_t)(((moff + CHUNK + 3) >> 2) << 4);   // 10800
    const uint32_t wbytes = (uint32_t)(((woff + TXH + 3) >> 2) << 4);     // 160

    if (tid == 0) {
        mbar_init(mbarA, 1);
        mbar_init(mbarB, 1);
        asm volatile("fence.proxy.async.shared::cta;" ::: "memory");
    }
    __syncthreads();

    if (tid == 0) {
        const uint32_t svalA = smem_u32(sval);
        const uint32_t swtA  = smem_u32(swt);

        mbar_expect(mbarA, GROUP_A_ROWS * (vbytes + wbytes));
        #pragma unroll
        for (int c = 0; c < GROUP_A_ROWS; c++) {
            const int rbase = (ybase + c) * PW + xbase;
            bulk_g2s(svalA + (uint32_t)(c * CSTRIDE) * 4,
                     dptr + (size_t)rbase * PDIM - moff, vbytes, mbarA);
            bulk_g2s(swtA + (uint32_t)(c * WSTRIDE) * 4,
                     wptr + rbase - woff, wbytes, mbarA);
        }
        mbar_expect(mbarB, (TYH - GROUP_A_ROWS) * (vbytes + wbytes));
        #pragma unroll
        for (int c = GROUP_A_ROWS; c < TYH; c++) {
            const int rbase = (ybase + c) * PW + xbase;
            bulk_g2s(svalA + (uint32_t)(c * CSTRIDE) * 4,
                     dptr + (size_t)rbase * PDIM - moff, vbytes, mbarB);
            bulk_g2s(swtA + (uint32_t)(c * WSTRIDE) * 4,
                     wptr + rbase - woff, wbytes, mbarB);
        }
    }

    // Overlap with DMA: reduce the means partials
    if (tid < 6) {
        float s = 0.f;
        #pragma unroll
        for (int k = 0; k < MEANS_CHUNKS; k++) s += g_part[tid * MEANS_CHUNKS + k];
        smeans[tid] = s * (1.0f / (float)(OH * OW));
    }

    const int tx = tid & (TX - 1);
    const int ty = tid >> 5;                    // warp id == output row
    const bool ph1 = (yoff + ty + 4 <= GROUP_A_ROWS - 1);

    const float* svalc = sval + moff;
    const float* swtc  = swt + woff;

    mbar_wait0(mbarA);     // group A rows landed
    __syncthreads();       // smeans visible CTA-wide

    if (ph1)
        gather_row(svalc, swtc, smeans, t, ty, tx, x0, y0, xoff, yoff, out);

    mbar_wait0(mbarB);     // group B rows landed

    if (!ph1)
        gather_row(svalc, swtc, smeans, t, ty, tx, x0, y0, xoff, yoff, out);
}

// ---------------- launch ------------------------------------------------------
extern "C" void kernel_launch(void* const* d_in, const int* in_sizes, int n_in,
                              void* d_out, int out_size) {
    const float* noisy = (const float*)d_in[0];
    const float* deno  = (const float*)d_in[1];
    const float* pwts  = (const float*)d_in[2];
    float* out = (float*)d_out;

    cudaFuncSetAttribute(fold_kernel,
                         cudaFuncAttributeMaxDynamicSharedMemorySize,
                         SMEM_BYTES);

    dim3 mg(6, MEANS_CHUNKS);
    means_partial_kernel<<<mg, 512>>>(noisy);

    dim3 grid((OW + TX - 1) / TX, (OH + TY - 1) / TY, NT);
    fold_kernel<<<grid, THREADS, SMEM_BYTES>>>(deno, pwts, out);
}

// round 8
// speedup vs baseline: 10.3102x; 1.1037x over previous
#include <cuda_runtime.h>
#include <cstdint>

#define PS 5
#define NT 2
#define PH 536
#define PW 536
#define OH 532
#define OW 532
#define PDIM 75
#define HW (PH*PW)

#define TX 32
#define TXH (TX+4)            // 36
#define CHUNK (TXH*PDIM)      // 2700 floats per patch row window
#define CSTRIDE 2700          // 10800 B, 16B-aligned
#define WSTR 40               // weight slot stride (160 B)
#define RING 20               // row-ring slots
#define RPS 8                 // output rows per stage
#define NB 4                  // stage mbarriers
#define TPB 256
#define NSTRIPS 4
#define SROWS 133             // 4*133 = 532
#define VBYTES 10800          // CHUNK*4
#define WBYTES 144            // TXH*4

// smem layout (floats)
#define SVAL_OFF   0
#define SWT_OFF    (RING*CSTRIDE)             // 54000
#define SMEANS_OFF (SWT_OFF + RING*WSTR)      // 54800
#define MBAR_OFF   (SMEANS_OFF + 8)           // 54808 (byte 219232, 16B aligned)
#define SMEM_FLOATS (MBAR_OFF + 2*NB)
#define SMEM_BYTES  (SMEM_FLOATS*4)           // 219,264 B

#define MEANS_CHUNKS 32       // 6*32 = 192 blocks

__device__ float g_part[6 * MEANS_CHUNKS];

// ---------------- PTX helpers ------------------------------------------------
__device__ __forceinline__ uint32_t smem_u32(const void* p) {
    return (uint32_t)__cvta_generic_to_shared(p);
}
__device__ __forceinline__ void mbar_init(uint32_t a, uint32_t cnt) {
    asm volatile("mbarrier.init.shared.b64 [%0], %1;" :: "r"(a), "r"(cnt) : "memory");
}
__device__ __forceinline__ void mbar_expect(uint32_t a, uint32_t bytes) {
    asm volatile("mbarrier.arrive.expect_tx.shared.b64 _, [%0], %1;"
                 :: "r"(a), "r"(bytes) : "memory");
}
__device__ __forceinline__ void mbar_wait(uint32_t a, uint32_t parity) {
    asm volatile(
        "{\n\t.reg .pred P;\n\t"
        "WL_%=:\n\t"
        "mbarrier.try_wait.parity.shared.b64 P, [%0], %1, 0x989680;\n\t"
        "@P bra.uni WD_%=;\n\t"
        "bra.uni WL_%=;\n\t"
        "WD_%=:\n\t}"
        :: "r"(a), "r"(parity) : "memory");
}
__device__ __forceinline__ void bulk_g2s(uint32_t dst, const void* src,
                                         uint32_t bytes, uint32_t mbar) {
    asm volatile(
        "cp.async.bulk.shared::cta.global.mbarrier::complete_tx::bytes "
        "[%0], [%1], %2, [%3];"
        :: "r"(dst), "l"(src), "r"(bytes), "r"(mbar) : "memory");
}

// ---------------- means: partial sums ----------------------------------------
__global__ void __launch_bounds__(512)
means_partial_kernel(const float* __restrict__ noisy) {
    int tc    = blockIdx.x;
    int chunk = blockIdx.y;
    const int plane = OH * OW;
    const float4* p = (const float4*)(noisy + (size_t)tc * plane);
    const int n4 = plane / 4;
    float s = 0.f;
    #pragma unroll 8
    for (int i = chunk * 512 + threadIdx.x; i < n4; i += MEANS_CHUNKS * 512) {
        float4 v = p[i];
        s += (v.x + v.y) + (v.z + v.w);
    }
    __shared__ float red[32];
    #pragma unroll
    for (int o = 16; o; o >>= 1) s += __shfl_down_sync(0xffffffffu, s, o);
    if ((threadIdx.x & 31) == 0) red[threadIdx.x >> 5] = s;
    __syncthreads();
    if (threadIdx.x < 32) {
        float v = (threadIdx.x < 16) ? red[threadIdx.x] : 0.f;
        #pragma unroll
        for (int o = 16; o; o >>= 1) v += __shfl_down_sync(0xffffffffu, v, o);
        if (threadIdx.x == 0) g_part[tc * MEANS_CHUNKS + chunk] = v;
    }
}

// ---------------- persistent fold kernel --------------------------------------
extern __shared__ float smem[];

__global__ void __launch_bounds__(TPB, 1)
fold_kernel(const float* __restrict__ deno,
            const float* __restrict__ pwts,
            float* __restrict__ out) {
    const int t     = blockIdx.z;
    const int strip = blockIdx.y;
    const int x0    = blockIdx.x * TX;
    const int xbase = min(x0, PW - TXH);
    const int xoff  = x0 - xbase;

    const int ys = strip * SROWS;
    const int ye = min(ys + SROWS, OH);
    const int nstages = (ye - ys + RPS - 1) / RPS;

    const float* dptr = deno + (size_t)t * HW * PDIM;
    const float* wptr = pwts + (size_t)t * HW;

    float* sval   = smem + SVAL_OFF;
    float* swt    = smem + SWT_OFF;
    float* smeans = smem + SMEANS_OFF;
    const uint32_t mb0   = smem_u32(smem + MBAR_OFF);
    const uint32_t svalA = smem_u32(sval);
    const uint32_t swtA  = smem_u32(swt);

    const int tid = threadIdx.x;
    const int tx  = tid & 31;
    const int wid = tid >> 5;          // output row within stage
    const int Xo  = x0 + tx;

    if (tid < NB) mbar_init(mb0 + tid * 8, 1);
    __syncthreads();

    // Prologue: stage 0 needs patch rows [ys, min(ys+12, ye+4))
    if (tid == 0) {
        asm volatile("fence.proxy.async.shared::cta;" ::: "memory");
        const int r0 = ys, r1 = min(ys + RPS + 4, ye + 4);
        mbar_expect(mb0, (uint32_t)((r1 - r0) * (VBYTES + WBYTES)));
        for (int r = r0; r < r1; r++) {
            const int slot  = r % RING;
            const int rbase = r * PW + xbase;
            bulk_g2s(svalA + (uint32_t)(slot * CSTRIDE) * 4,
                     dptr + (size_t)rbase * PDIM, VBYTES, mb0);
            bulk_g2s(swtA + (uint32_t)(slot * WSTR) * 4,
                     wptr + rbase, WBYTES, mb0);
        }
    }
    // Overlap with DMA: reduce means partials into smem
    if (tid < 6) {
        float s = 0.f;
        #pragma unroll
        for (int k = 0; k < MEANS_CHUNKS; k++) s += g_part[tid * MEANS_CHUNKS + k];
        smeans[tid] = s * (1.0f / (float)(OH * OW));
    }
    __syncthreads();   // smeans visible CTA-wide

    const float m0 = smeans[t * 3 + 0];
    const float m1 = smeans[t * 3 + 1];
    const float m2 = smeans[t * 3 + 2];
    const size_t plane = (size_t)OH * OW;
    const int lxb = xoff + tx;

    for (int s = 0; s < nstages; s++) {
        // Prefetch stage s+1's new rows (depth-1 ahead; slot reuse is safe:
        // these slots last held stage s-1's rows, done by last syncthreads)
        if (tid == 0 && s + 1 < nstages) {
            const int r0 = ys + RPS * s + RPS + 4;         // = ys+8s+12
            const int r1 = min(ys + RPS * (s + 1) + RPS + 4, ye + 4);
            const uint32_t mb = mb0 + ((s + 1) % NB) * 8;
            mbar_expect(mb, (uint32_t)((r1 - r0) * (VBYTES + WBYTES)));
            for (int r = r0; r < r1; r++) {
                const int slot  = r % RING;
                const int rbase = r * PW + xbase;
                bulk_g2s(svalA + (uint32_t)(slot * CSTRIDE) * 4,
                         dptr + (size_t)rbase * PDIM, VBYTES, mb);
                bulk_g2s(swtA + (uint32_t)(slot * WSTR) * 4,
                         wptr + rbase, WBYTES, mb);
            }
        }

        mbar_wait(mb0 + (s % NB) * 8, (uint32_t)((s >> 2) & 1));

        const int Yo = ys + RPS * s + wid;
        if (Yo < ye && Xo < OW) {
            const int sb = (ys + RPS * s) % RING;   // ring slot of stage base row

            float a0 = 0.f, a1 = 0.f, a2 = 0.f, cnt = 0.f;
            #pragma unroll
            for (int i = 0; i < PS; i++) {
                int sl = sb + wid + 4 - i;          // patch row Yo+4-i
                if (sl >= RING) sl -= RING;
                const float* vrow = sval + sl * CSTRIDE;
                const float* wrow = swt + sl * WSTR;
                #pragma unroll
                for (int j = 0; j < PS; j++) {
                    const int lx = lxb + 4 - j;
                    const float w = wrow[lx];
                    const float* v = vrow + lx * PDIM;  // stride 75: conflict-free
                    const int sidx = i * PS + j;
                    cnt += w;
                    a0 = fmaf(v[sidx],      w, a0);
                    a1 = fmaf(v[25 + sidx], w, a1);
                    a2 = fmaf(v[50 + sidx], w, a2);
                }
            }

            const float inv = 0.5f / cnt;
            size_t o = (size_t)t * 3 * plane + (size_t)Yo * OW + Xo;
            out[o]             = a0 * inv + m0;
            out[o + plane]     = a1 * inv + m1;
            out[o + 2 * plane] = a2 * inv + m2;
        }
        __syncthreads();   // stage boundary: protects ring-slot reuse
    }
}

// ---------------- launch ------------------------------------------------------
extern "C" void kernel_launch(void* const* d_in, const int* in_sizes, int n_in,
                              void* d_out, int out_size) {
    const float* noisy = (const float*)d_in[0];
    const float* deno  = (const float*)d_in[1];
    const float* pwts  = (const float*)d_in[2];
    float* out = (float*)d_out;

    cudaFuncSetAttribute(fold_kernel,
                         cudaFuncAttributeMaxDynamicSharedMemorySize,
                         SMEM_BYTES);

    dim3 mg(6, MEANS_CHUNKS);
    means_partial_kernel<<<mg, 512>>>(noisy);

    dim3 grid((OW + TX - 1) / TX, NSTRIPS, NT);   // 17 x 4 x 2 = 136 CTAs, one wave
    fold_kernel<<<grid, TPB, SMEM_BYTES>>>(deno, pwts, out);
}